// round 2
// baseline (speedup 1.0000x reference)
#include <cuda_runtime.h>
#include <cstdint>

// FilterbankEdge: three per-position linears.
//   x: (64, 21, 1368) f32
//   FB0: w=16 s=4  d=64  P=338 K=336   out cols [0,     21632)
//   FB1: w=32 s=8  d=128 P=167 K=672   out cols [21632, 43008)
//   FB2: w=64 s=16 d=256 P=82  K=1344  out cols [43008, 64000)
// For p < P-1: start = p*s; last position: start = 1368 - w.
// h[b, p*d + dd] = sum_{q,j} x[b, q, start+j] * W[(p*d+dd)*K + q*w + j]

#define B_DIM 64
#define Q_DIM 21
#define N_DIM 1368
#define OUT_W 64000
#define BK 16

typedef unsigned long long ull;

__device__ __forceinline__ void fma2(ull& c, ull a, ull b) {
    // packed f32x2 FMA (sm_100+): lane-wise fp32 fma
    asm("fma.rn.f32x2 %0, %1, %2, %0;" : "+l"(c) : "l"(a), "l"(b));
}

template<int LW, int KTOT, int D, int BN>
__device__ __forceinline__ void fb_tile(
    const float* __restrict__ x, const float* __restrict__ Wt,
    float* __restrict__ out, int p, int P, int ntile, int outBase,
    float (*As)[BK][68], float (*Bs)[BK][260])
{
    constexpr int W  = 1 << LW;
    constexpr int S  = W >> 2;          // stride = w/4 for all three banks
    constexpr int KT = KTOT / BK;       // exact: 336/672/1344 all %16==0
    constexpr int NJ = BN / 16;         // n outputs per thread (4 or 8)
    constexpr int NB = BN / 32;         // B-tile float4 loads per thread

    const int tid = threadIdx.x;
    const int k4  = tid & 3;            // which float4 along k
    const int r   = tid >> 2;           // 0..31 row group
    const int tx  = tid & 15;           // n-dim thread coord
    const int ty  = tid >> 4;           // m-dim thread coord (0..7)

    const int start = (p == P - 1) ? (N_DIM - W) : p * S;
    const float* Wblk = Wt + (size_t)(p * D + ntile * BN) * KTOT;

    float4 aReg[2];
    float4 bReg[NB];

    ull c[4][NJ];
    #pragma unroll
    for (int u = 0; u < 4; u++)
        #pragma unroll
        for (int j = 0; j < NJ; j++) c[u][j] = 0ull;

    // ---- global -> regs for k-tile kt
    auto loadT = [&](int kt) {
        const int kk = kt * BK + k4 * 4;     // global k of this float4
        const int q  = kk >> LW;
        const int jj = kk & (W - 1);         // stays within one window row (w>=16, 4-aligned)
        const float* pa = x + r * (Q_DIM * N_DIM) + q * N_DIM + start + jj;
        aReg[0] = *(const float4*)pa;
        aReg[1] = *(const float4*)(pa + 32 * (Q_DIM * N_DIM));
        const float* pb = Wblk + (size_t)r * KTOT + kk;
        #pragma unroll
        for (int i = 0; i < NB; i++)
            bReg[i] = *(const float4*)(pb + (size_t)(32 * i) * KTOT);
    };
    // ---- regs -> smem (A transposed [k][m]; B transposed + value-duplicated [k][2n])
    auto storeT = [&](int buf) {
        #pragma unroll
        for (int i = 0; i < 2; i++) {
            const float* v = (const float*)&aReg[i];
            #pragma unroll
            for (int cc = 0; cc < 4; cc++)
                As[buf][k4 * 4 + cc][r + 32 * i] = v[cc];
        }
        #pragma unroll
        for (int i = 0; i < NB; i++) {
            const float* v = (const float*)&bReg[i];
            #pragma unroll
            for (int cc = 0; cc < 4; cc++) {
                float2 d2 = make_float2(v[cc], v[cc]);
                *(float2*)&Bs[buf][k4 * 4 + cc][2 * (r + 32 * i)] = d2;
            }
        }
    };
    auto compute = [&](int buf) {
        #pragma unroll
        for (int k = 0; k < BK; k++) {
            ull a[4];
            #pragma unroll
            for (int u = 0; u < 4; u++)
                a[u] = *(const ull*)&As[buf][k][ty * 8 + 2 * u];  // m-pair in f32x2 lanes
            ull b[NJ];
            #pragma unroll
            for (int t = 0; t < NJ / 2; t++) {
                ulonglong2 bb = *(const ulonglong2*)&Bs[buf][k][tx * (2 * NJ) + 4 * t];
                b[2 * t] = bb.x; b[2 * t + 1] = bb.y;             // each = (v_n, v_n)
            }
            #pragma unroll
            for (int u = 0; u < 4; u++)
                #pragma unroll
                for (int j = 0; j < NJ; j++)
                    fma2(c[u][j], a[u], b[j]);
        }
    };

    // double-buffered mainloop: one barrier per K-tile
    loadT(0);
    storeT(0);
    __syncthreads();

    for (int kt = 0; kt < KT; kt++) {
        if (kt + 1 < KT) loadT(kt + 1);      // prefetch next tile into regs
        compute(kt & 1);
        if (kt + 1 < KT) {
            storeT((kt + 1) & 1);            // other buffer: no hazard with compute
            __syncthreads();
        }
    }

    // ---- writeout: c[u][j] lanes = (m0, m0+1) for column col0+j
    const int col0 = outBase + p * D + ntile * BN + tx * NJ;
    #pragma unroll
    for (int u = 0; u < 4; u++) {
        const int m0 = ty * 8 + 2 * u;
        float lo[NJ], hi[NJ];
        #pragma unroll
        for (int j = 0; j < NJ; j++) {
            union { ull u64; float2 f; } cv; cv.u64 = c[u][j];
            lo[j] = cv.f.x; hi[j] = cv.f.y;
        }
        float* po = out + (size_t)m0 * OUT_W + col0;
        #pragma unroll
        for (int t = 0; t < NJ / 4; t++) {
            *(float4*)(po + 4 * t)         = make_float4(lo[4*t], lo[4*t+1], lo[4*t+2], lo[4*t+3]);
            *(float4*)(po + OUT_W + 4 * t) = make_float4(hi[4*t], hi[4*t+1], hi[4*t+2], hi[4*t+3]);
        }
    }
}

// Grid layout (longest-K first for tail balance):
//   [0,164):   FB2, p = bid>>1, ntile = bid&1   (BN=128, two N-tiles of 256)
//   [164,331): FB1, p = bid-164                 (BN=128)
//   [331,669): FB0, p = bid-331                 (BN=64)
__global__ void __launch_bounds__(128)
fb_kernel(const float* __restrict__ x, const float* __restrict__ w0,
          const float* __restrict__ w1, const float* __restrict__ w2,
          float* __restrict__ out)
{
    __shared__ __align__(16) float As[2][BK][68];
    __shared__ __align__(16) float Bs[2][BK][260];
    const int bid = blockIdx.x;
    if (bid < 164)
        fb_tile<6, 1344, 256, 128>(x, w2, out, bid >> 1, 82, bid & 1, 43008, As, Bs);
    else if (bid < 331)
        fb_tile<5, 672, 128, 128>(x, w1, out, bid - 164, 167, 0, 21632, As, Bs);
    else
        fb_tile<4, 336, 64, 64>(x, w0, out, bid - 331, 338, 0, 0, As, Bs);
}

extern "C" void kernel_launch(void* const* d_in, const int* in_sizes, int n_in,
                              void* d_out, int out_size)
{
    (void)in_sizes; (void)n_in; (void)out_size;
    const float* x  = (const float*)d_in[0];
    const float* w0 = (const float*)d_in[1];
    const float* w1 = (const float*)d_in[2];
    const float* w2 = (const float*)d_in[3];
    fb_kernel<<<669, 128>>>(x, w0, w1, w2, (float*)d_out);
}

// round 3
// speedup vs baseline: 2.9508x; 2.9508x over previous
#include <cuda_runtime.h>
#include <cstdint>

// FilterbankEdge: three per-position linears.
//   x: (64, 21, 1368) f32
//   FB0: w=16 s=4  d=64  P=338 K=336   out cols [0,     21632)
//   FB1: w=32 s=8  d=128 P=167 K=672   out cols [21632, 43008)
//   FB2: w=64 s=16 d=256 P=82  K=1344  out cols [43008, 64000)
// For p < P-1: start = p*s; last position: start = 1368 - w.
// h[b, p*d + dd] = sum_{q,j} x[b, q, start+j] * W[(p*d+dd)*K + q*w + j]

#define B_DIM 64
#define Q_DIM 21
#define N_DIM 1368
#define OUT_W 64000
#define BK 16
#define BROW 192   // B smem row: 16 tx-blocks x 3 slots x 4 floats (2 data + 1 pad slot)

typedef unsigned long long ull;

__device__ __forceinline__ void fma2(ull& c, ull a, ull b) {
    // packed f32x2 FMA (sm_100+): lane-wise fp32 fma
    asm("fma.rn.f32x2 %0, %1, %2, %0;" : "+l"(c) : "l"(a), "l"(b));
}
__device__ __forceinline__ ull dup2(float v) {
    ull r;
    asm("mov.b64 %0, {%1, %1};" : "=l"(r) : "f"(v));
    return r;
}

template<int LW, int KTOT, int D, int BN>
__device__ __forceinline__ void fb_tile(
    const float* __restrict__ x, const float* __restrict__ Wt,
    float* __restrict__ out, int p, int P, int ntile, int outBase,
    float (*As)[BK][68], float (*Bs)[BK][BROW])
{
    constexpr int W  = 1 << LW;
    constexpr int S  = W >> 2;          // stride = w/4 for all three banks
    constexpr int KT = KTOT / BK;       // exact: 336/672/1344 all %16==0
    constexpr int NJ = BN / 16;         // n outputs per thread (4 or 8)
    constexpr int NB = BN / 32;         // B-tile float4 loads per thread
    constexpr int NR = NJ / 4;          // B LDS.128 per k (1 or 2)

    const int tid = threadIdx.x;
    const int k4  = tid & 3;            // which float4 along k
    const int r   = tid >> 2;           // 0..31 row group
    const int tx  = tid & 15;           // n-dim thread coord
    const int ty  = tid >> 4;           // m-dim thread coord (0..7)

    const int start = (p == P - 1) ? (N_DIM - W) : p * S;
    const float* Wblk = Wt + (size_t)(p * D + ntile * BN) * KTOT;

    float4 aReg[2];
    float4 bReg[NB];

    ull c[4][NJ];
    #pragma unroll
    for (int u = 0; u < 4; u++)
        #pragma unroll
        for (int j = 0; j < NJ; j++) c[u][j] = 0ull;

    // ---- global -> regs for k-tile kt
    auto loadT = [&](int kt) {
        const int kk = kt * BK + k4 * 4;     // global k of this float4
        const int q  = kk >> LW;
        const int jj = kk & (W - 1);         // stays within one window row (w>=16, 4-aligned)
        const float* pa = x + r * (Q_DIM * N_DIM) + q * N_DIM + start + jj;
        aReg[0] = *(const float4*)pa;
        aReg[1] = *(const float4*)(pa + 32 * (Q_DIM * N_DIM));
        const float* pb = Wblk + (size_t)r * KTOT + kk;
        #pragma unroll
        for (int i = 0; i < NB; i++)
            bReg[i] = *(const float4*)(pb + (size_t)(32 * i) * KTOT);
    };
    // ---- regs -> smem
    // A transposed [k][m] (broadcast-read later).
    // B transposed [k][n], n packed into per-tx 48B blocks (2 data slots + 1 pad
    // slot) so 8-lane LDS.128 phases hit distinct bank groups: tx*3+t mod 8 is a
    // permutation -> conflict-free.
    auto storeT = [&](int buf) {
        #pragma unroll
        for (int i = 0; i < 2; i++) {
            const float* v = (const float*)&aReg[i];
            #pragma unroll
            for (int cc = 0; cc < 4; cc++)
                As[buf][k4 * 4 + cc][r + 32 * i] = v[cc];
        }
        #pragma unroll
        for (int i = 0; i < NB; i++) {
            const int vn = r + 32 * i;                    // n index in tile
            const int phys = (vn / NJ) * 12 + (vn % NJ);  // padded position
            const float* v = (const float*)&bReg[i];
            #pragma unroll
            for (int cc = 0; cc < 4; cc++)
                Bs[buf][k4 * 4 + cc][phys] = v[cc];
        }
    };
    auto compute = [&](int buf) {
        #pragma unroll
        for (int k = 0; k < BK; k++) {
            ull a[4];
            #pragma unroll
            for (int u = 0; u < 4; u++)
                a[u] = *(const ull*)&As[buf][k][ty * 8 + 2 * u];  // m-pair in f32x2 lanes
            ull b[NJ];
            #pragma unroll
            for (int t = 0; t < NR; t++) {
                float4 bf = *(const float4*)&Bs[buf][k][tx * 12 + 4 * t];
                b[4 * t + 0] = dup2(bf.x);
                b[4 * t + 1] = dup2(bf.y);
                b[4 * t + 2] = dup2(bf.z);
                b[4 * t + 3] = dup2(bf.w);
            }
            #pragma unroll
            for (int u = 0; u < 4; u++)
                #pragma unroll
                for (int j = 0; j < NJ; j++)
                    fma2(c[u][j], a[u], b[j]);
        }
    };

    // double-buffered mainloop: one barrier per K-tile
    loadT(0);
    storeT(0);
    __syncthreads();

    for (int kt = 0; kt < KT; kt++) {
        if (kt + 1 < KT) loadT(kt + 1);      // prefetch next tile into regs
        compute(kt & 1);
        if (kt + 1 < KT) {
            storeT((kt + 1) & 1);            // other buffer: no hazard with compute
            __syncthreads();
        }
    }

    // ---- writeout: c[u][j] lanes = (m0, m0+1) for column col0+j
    const int col0 = outBase + p * D + ntile * BN + tx * NJ;
    #pragma unroll
    for (int u = 0; u < 4; u++) {
        const int m0 = ty * 8 + 2 * u;
        float lo[NJ], hi[NJ];
        #pragma unroll
        for (int j = 0; j < NJ; j++) {
            union { ull u64; float2 f; } cv; cv.u64 = c[u][j];
            lo[j] = cv.f.x; hi[j] = cv.f.y;
        }
        float* po = out + (size_t)m0 * OUT_W + col0;
        #pragma unroll
        for (int t = 0; t < NJ / 4; t++) {
            *(float4*)(po + 4 * t)         = make_float4(lo[4*t], lo[4*t+1], lo[4*t+2], lo[4*t+3]);
            *(float4*)(po + OUT_W + 4 * t) = make_float4(hi[4*t], hi[4*t+1], hi[4*t+2], hi[4*t+3]);
        }
    }
}

// Grid layout (longest-K first for tail balance):
//   [0,164):   FB2, p = bid>>1, ntile = bid&1   (BN=128, two N-tiles of 256)
//   [164,331): FB1, p = bid-164                 (BN=128)
//   [331,669): FB0, p = bid-331                 (BN=64)
__global__ void __launch_bounds__(128)
fb_kernel(const float* __restrict__ x, const float* __restrict__ w0,
          const float* __restrict__ w1, const float* __restrict__ w2,
          float* __restrict__ out)
{
    __shared__ __align__(16) float As[2][BK][68];
    __shared__ __align__(16) float Bs[2][BK][BROW];
    const int bid = blockIdx.x;
    if (bid < 164)
        fb_tile<6, 1344, 256, 128>(x, w2, out, bid >> 1, 82, bid & 1, 43008, As, Bs);
    else if (bid < 331)
        fb_tile<5, 672, 128, 128>(x, w1, out, bid - 164, 167, 0, 21632, As, Bs);
    else
        fb_tile<4, 336, 64, 64>(x, w0, out, bid - 331, 338, 0, 0, As, Bs);
}

extern "C" void kernel_launch(void* const* d_in, const int* in_sizes, int n_in,
                              void* d_out, int out_size)
{
    (void)in_sizes; (void)n_in; (void)out_size;
    const float* x  = (const float*)d_in[0];
    const float* w0 = (const float*)d_in[1];
    const float* w1 = (const float*)d_in[2];
    const float* w2 = (const float*)d_in[3];
    fb_kernel<<<669, 128>>>(x, w0, w1, w2, (float*)d_out);
}

// round 7
// speedup vs baseline: 4.8100x; 1.6301x over previous
#include <cuda_runtime.h>
#include <cuda_bf16.h>
#include <cstdint>

// FilterbankEdge hybrid:
//   FB0 (w=16 s=4  d=64  P=338 K=336)  -> FFMA2 path (round-3 proven), cols [0,21632)
//   FB1 (w=32 s=8  d=128 P=167 K=672)  -> mma.sync bf16 split, cols [21632,43008)
//   FB2 (w=64 s=16 d=256 P=82  K=1344) -> mma.sync bf16 split, cols [43008,64000)
// x: (64, 21, 1368) f32. h[b, p*d+dd] = sum_k win[b,k] * W[p*d+dd, k].
// MMA: A = x window (M=64 batch, row-major), B = W (N cols, "col" = [n][k]),
// D[m=batch][n=weight col] -> direct store. 2-term bf16 split, 3 products.

#define Q_DIM 21
#define N_DIM 1368
#define XROW (Q_DIM * N_DIM)
#define OUT_W 64000
#define BK 16
#define BROW 192

typedef unsigned long long ull;
typedef unsigned int u32;

__device__ __forceinline__ u32 smem_u32(const void* p) {
    u32 a;
    asm("{ .reg .u64 t; cvta.to.shared.u64 t, %1; cvt.u32.u64 %0, t; }" : "=r"(a) : "l"(p));
    return a;
}
__device__ __forceinline__ void ldm_x4(u32* r, u32 addr) {
    asm volatile("ldmatrix.sync.aligned.m8n8.x4.shared.b16 {%0,%1,%2,%3}, [%4];"
                 : "=r"(r[0]), "=r"(r[1]), "=r"(r[2]), "=r"(r[3]) : "r"(addr));
}
__device__ __forceinline__ void mma_bf16(float* d, const u32* a, const u32* b) {
    asm("mma.sync.aligned.m16n8k16.row.col.f32.bf16.bf16.f32 "
        "{%0,%1,%2,%3}, {%4,%5,%6,%7}, {%8,%9}, {%0,%1,%2,%3};"
        : "+f"(d[0]), "+f"(d[1]), "+f"(d[2]), "+f"(d[3])
        : "r"(a[0]), "r"(a[1]), "r"(a[2]), "r"(a[3]), "r"(b[0]), "r"(b[1]));
}
__device__ __forceinline__ void split4(float4 v, uint2& hi, uint2& lo) {
    __nv_bfloat162 h0 = __float22bfloat162_rn(make_float2(v.x, v.y));
    __nv_bfloat162 h1 = __float22bfloat162_rn(make_float2(v.z, v.w));
    float2 f0 = __bfloat1622float2(h0), f1 = __bfloat1622float2(h1);
    __nv_bfloat162 l0 = __float22bfloat162_rn(make_float2(v.x - f0.x, v.y - f0.y));
    __nv_bfloat162 l1 = __float22bfloat162_rn(make_float2(v.z - f1.x, v.w - f1.y));
    hi = make_uint2(*(u32*)&h0, *(u32*)&h1);
    lo = make_uint2(*(u32*)&l0, *(u32*)&l1);
}

// ---- MMA-path SMEM layout (bytes). Rows padded to 24 halves (48 B):
//   12*m mod 32 is a permutation over any 8 consecutive rows -> conflict-free
//   STS.64 and ldmatrix phases.
// XA: x tiles   [2 buf][2 split][64 rows][24 halves]  = 12288 B
// WB: W tiles   [2 buf][2 split][128 rows][24 halves] = 24576 B
#define WB_OFF 12288
#define SMEM_BYTES 36864

// =================== tensor path (FB1 / FB2) ===================
template<int LW, int KTOT, int D>
__device__ __forceinline__ void fb_mma(
    const float* __restrict__ x, const float* __restrict__ Wt,
    float* __restrict__ out, int p, int P, int mtile, int outBase, char* dsm)
{
    constexpr int W  = 1 << LW;
    constexpr int S  = W >> 2;
    constexpr int KT = KTOT / 16;

    const int tid   = threadIdx.x;
    const int lane  = tid & 31;
    const int wid   = tid >> 5;
    const int warpM = wid & 1;      // 2 warps along M=64 (batch)
    const int warpN = wid >> 1;     // 2 warps along N=128 (weight cols)

    const int start = (p == P - 1) ? (N_DIM - W) : p * S;
    const float* Wblk = Wt + (size_t)(p * D + mtile * 128) * KTOT;
    const u32 sb = smem_u32(dsm);

    // loader coords: 4 threads x float4 = one 16-float k-chunk row
    const int kx   = (tid & 3) * 4;
    const int lrow = tid >> 2;          // 0..31

    float4 va[2], vb[4];
    auto loadRegs = [&](int c) {
        const int k = c * 16 + kx;
        const int q = k >> LW, j = k & (W - 1);
        const float* pa = x + (size_t)lrow * XROW + q * N_DIM + start + j;
        va[0] = *(const float4*)pa;
        va[1] = *(const float4*)(pa + 32 * XROW);
        #pragma unroll
        for (int i = 0; i < 4; i++)
            vb[i] = *(const float4*)(Wblk + (size_t)(lrow + 32 * i) * KTOT + k);
    };
    auto stsAll = [&](int buf) {
        #pragma unroll
        for (int i = 0; i < 2; i++) {
            uint2 hi, lo; split4(va[i], hi, lo);
            const int m = lrow + 32 * i;
            *(uint2*)(dsm + ((buf * 2 + 0) * 64 + m) * 48 + kx * 2) = hi;
            *(uint2*)(dsm + ((buf * 2 + 1) * 64 + m) * 48 + kx * 2) = lo;
        }
        #pragma unroll
        for (int i = 0; i < 4; i++) {
            uint2 hi, lo; split4(vb[i], hi, lo);
            const int n = lrow + 32 * i;
            *(uint2*)(dsm + WB_OFF + ((buf * 2 + 0) * 128 + n) * 48 + kx * 2) = hi;
            *(uint2*)(dsm + WB_OFF + ((buf * 2 + 1) * 128 + n) * 48 + kx * 2) = lo;
        }
    };

    float d[2][8][4];
    #pragma unroll
    for (int mi = 0; mi < 2; mi++)
        #pragma unroll
        for (int nf = 0; nf < 8; nf++)
            #pragma unroll
            for (int u = 0; u < 4; u++) d[mi][nf][u] = 0.f;

    // A-frag lane addressing (m16k16 via x4): tiles (r0..r3) =
    // (m0-7,k0-7),(m8-15,k0-7),(m0-7,k8-15),(m8-15,k8-15)
    const int aRow = (lane & 7) + 8 * ((lane >> 3) & 1);
    const int aKh  = (lane >> 4) * 8;
    // B-frag pair (two n8k16 frags per x4): tiles =
    // (n0-7,k0-7),(n0-7,k8-15),(n8-15,k0-7),(n8-15,k8-15)
    const int bRow = (lane & 7) + ((lane >> 4) & 1) * 8;
    const int bKh  = ((lane >> 3) & 1) * 8;

    auto compute = [&](int buf) {
        u32 ah[2][4], al[2][4];
        #pragma unroll
        for (int mi = 0; mi < 2; mi++) {
            const int m = warpM * 32 + mi * 16 + aRow;
            ldm_x4(ah[mi], sb + ((buf * 2 + 0) * 64 + m) * 48 + aKh * 2);
            ldm_x4(al[mi], sb + ((buf * 2 + 1) * 64 + m) * 48 + aKh * 2);
        }
        #pragma unroll
        for (int nq = 0; nq < 4; nq++) {
            const int n = warpN * 64 + nq * 16 + bRow;
            u32 bh[4], bl[4];
            ldm_x4(bh, sb + WB_OFF + ((buf * 2 + 0) * 128 + n) * 48 + bKh * 2);
            ldm_x4(bl, sb + WB_OFF + ((buf * 2 + 1) * 128 + n) * 48 + bKh * 2);
            #pragma unroll
            for (int mi = 0; mi < 2; mi++)
                #pragma unroll
                for (int f = 0; f < 2; f++) {
                    float* acc = d[mi][2 * nq + f];
                    mma_bf16(acc, ah[mi], bh + 2 * f);   // Ah*Bh
                    mma_bf16(acc, ah[mi], bl + 2 * f);   // Ah*Bl
                    mma_bf16(acc, al[mi], bh + 2 * f);   // Al*Bh
                }
        }
    };

    loadRegs(0); stsAll(0); __syncthreads();
    for (int c = 0; c < KT; c++) {
        if (c + 1 < KT) loadRegs(c + 1);
        compute(c & 1);
        if (c + 1 < KT) { stsAll((c + 1) & 1); __syncthreads(); }
    }

    // ---- epilogue: D rows = batch, cols = weight rows -> direct store
    const int g = lane >> 2, t = lane & 3;
    #pragma unroll
    for (int mi = 0; mi < 2; mi++) {
        const int m0 = warpM * 32 + mi * 16 + g;
        #pragma unroll
        for (int nf = 0; nf < 8; nf++) {
            const int col = outBase + p * D + mtile * 128 + warpN * 64 + nf * 8 + 2 * t;
            float* po = out + (size_t)m0 * OUT_W + col;
            *(float2*)po = make_float2(d[mi][nf][0], d[mi][nf][1]);
            *(float2*)(po + (size_t)8 * OUT_W) = make_float2(d[mi][nf][2], d[mi][nf][3]);
        }
    }
}

// =================== FFMA path (FB0) — round-3 proven ===================
__device__ __forceinline__ void fma2(ull& c, ull a, ull b) {
    asm("fma.rn.f32x2 %0, %1, %2, %0;" : "+l"(c) : "l"(a), "l"(b));
}
__device__ __forceinline__ ull dup2(float v) {
    ull r; asm("mov.b64 %0, {%1, %1};" : "=l"(r) : "f"(v)); return r;
}

__device__ __forceinline__ void fb_tile_f0(
    const float* __restrict__ x, const float* __restrict__ Wt,
    float* __restrict__ out, int p, char* dsm)
{
    constexpr int LW = 4, W = 16, S = 4, KTOT = 336, D = 64;
    constexpr int KT = KTOT / BK, NJ = 4, NB = 2, NR = 1, P = 338;

    float (*As)[BK][68]   = (float (*)[BK][68])  (dsm);
    float (*Bs)[BK][BROW] = (float (*)[BK][BROW])(dsm + 2 * BK * 68 * 4);

    const int tid = threadIdx.x;
    const int k4 = tid & 3, r = tid >> 2, tx = tid & 15, ty = tid >> 4;
    const int start = (p == P - 1) ? (N_DIM - W) : p * S;
    const float* Wblk = Wt + (size_t)(p * D) * KTOT;

    float4 aReg[2]; float4 bReg[NB];
    ull c[4][NJ];
    #pragma unroll
    for (int u = 0; u < 4; u++)
        #pragma unroll
        for (int j = 0; j < NJ; j++) c[u][j] = 0ull;

    auto loadT = [&](int kt) {
        const int kk = kt * BK + k4 * 4;
        const int q = kk >> LW, jj = kk & (W - 1);
        const float* pa = x + r * XROW + q * N_DIM + start + jj;
        aReg[0] = *(const float4*)pa;
        aReg[1] = *(const float4*)(pa + 32 * XROW);
        const float* pb = Wblk + (size_t)r * KTOT + kk;
        #pragma unroll
        for (int i = 0; i < NB; i++)
            bReg[i] = *(const float4*)(pb + (size_t)(32 * i) * KTOT);
    };
    auto storeT = [&](int buf) {
        #pragma unroll
        for (int i = 0; i < 2; i++) {
            const float* v = (const float*)&aReg[i];
            #pragma unroll
            for (int cc = 0; cc < 4; cc++) As[buf][k4 * 4 + cc][r + 32 * i] = v[cc];
        }
        #pragma unroll
        for (int i = 0; i < NB; i++) {
            const int vn = r + 32 * i;
            const int phys = (vn / NJ) * 12 + (vn % NJ);
            const float* v = (const float*)&bReg[i];
            #pragma unroll
            for (int cc = 0; cc < 4; cc++) Bs[buf][k4 * 4 + cc][phys] = v[cc];
        }
    };
    auto compute = [&](int buf) {
        #pragma unroll
        for (int k = 0; k < BK; k++) {
            ull a[4];
            #pragma unroll
            for (int u = 0; u < 4; u++)
                a[u] = *(const ull*)&As[buf][k][ty * 8 + 2 * u];
            ull b[NJ];
            #pragma unroll
            for (int t = 0; t < NR; t++) {
                float4 bf = *(const float4*)&Bs[buf][k][tx * 12 + 4 * t];
                b[4*t+0] = dup2(bf.x); b[4*t+1] = dup2(bf.y);
                b[4*t+2] = dup2(bf.z); b[4*t+3] = dup2(bf.w);
            }
            #pragma unroll
            for (int u = 0; u < 4; u++)
                #pragma unroll
                for (int j = 0; j < NJ; j++) fma2(c[u][j], a[u], b[j]);
        }
    };

    loadT(0); storeT(0); __syncthreads();
    for (int kt = 0; kt < KT; kt++) {
        if (kt + 1 < KT) loadT(kt + 1);
        compute(kt & 1);
        if (kt + 1 < KT) { storeT((kt + 1) & 1); __syncthreads(); }
    }

    const int col0 = p * D + tx * NJ;
    #pragma unroll
    for (int u = 0; u < 4; u++) {
        const int m0 = ty * 8 + 2 * u;
        float lo[NJ], hi[NJ];
        #pragma unroll
        for (int j = 0; j < NJ; j++) {
            union { ull u64; float2 f; } cv; cv.u64 = c[u][j];
            lo[j] = cv.f.x; hi[j] = cv.f.y;
        }
        float* po = out + (size_t)m0 * OUT_W + col0;
        *(float4*)(po)         = make_float4(lo[0], lo[1], lo[2], lo[3]);
        *(float4*)(po + OUT_W) = make_float4(hi[0], hi[1], hi[2], hi[3]);
    }
}

// Grid: [0,164) FB2 MMA (p=bid>>1, mtile=bid&1); [164,331) FB1 MMA; [331,669) FB0 FFMA
__global__ void __launch_bounds__(128)
fb_kernel(const float* __restrict__ x, const float* __restrict__ w0,
          const float* __restrict__ w1, const float* __restrict__ w2,
          float* __restrict__ out)
{
    extern __shared__ char dsm[];
    const int bid = blockIdx.x;
    if (bid < 164)
        fb_mma<6, 1344, 256>(x, w2, out, bid >> 1, 82, bid & 1, 43008, dsm);
    else if (bid < 331)
        fb_mma<5, 672, 128>(x, w1, out, bid - 164, 167, 0, 21632, dsm);
    else
        fb_tile_f0(x, w0, out, bid - 331, dsm);
}

extern "C" void kernel_launch(void* const* d_in, const int* in_sizes, int n_in,
                              void* d_out, int out_size)
{
    (void)in_sizes; (void)n_in; (void)out_size;
    const float* x  = (const float*)d_in[0];
    const float* w0 = (const float*)d_in[1];
    const float* w1 = (const float*)d_in[2];
    const float* w2 = (const float*)d_in[3];
    fb_kernel<<<669, 128, SMEM_BYTES>>>(x, w0, w1, w2, (float*)d_out);
}